// round 16
// baseline (speedup 1.0000x reference)
#include <cuda_runtime.h>
#include <cuda_fp16.h>
#include <cooperative_groups.h>
#include <cstdint>

namespace cg = cooperative_groups;

#define PERIODS 12
#define ROWPAD 16          // xs/agg rows: 16 halves = 32B (1 sector)
#define HIDDEN 32
#define MAXN 100000
#define NPARAMS 173

// Scratch (static __device__ — zero-initialized at module load; every launch
// restores the zero-invariant itself).
__device__ float g_deg[MAXN];                             // invariant: 0 between launches
__device__ float g_dinv[MAXN];
__device__ __align__(32) __half g_aggh[MAXN * ROWPAD];    // invariant: 0 between launches
__device__ __align__(32) __half g_xsh[MAXN * ROWPAD];     // xs = dinv*x in fp16
__device__ float g_p[NPARAMS];
// layout: [0:32) vz*0.5 | [32:64) cz*0.5 | [64:96) vh | [96:128) ch
//         [128:160) hw | [160:172) probs | [172] head_b

__device__ __forceinline__ float tanhx(float x) {
    float y;
    asm("tanh.approx.f32 %0, %1;" : "=f"(y) : "f"(x));
    return y;
}

// One edge: agg[dst,:] += c * xs_row   (v4.f16x2 + v2.f16x2 reds; f32 products)
__device__ __forceinline__ void edge_one(int d, float c,
                                         const uint4 q0, const uint2 q1) {
    __half* ap = g_aggh + d * ROWPAD;

    float2 f0 = __half22float2(*(__half2*)&q0.x);
    float2 f1 = __half22float2(*(__half2*)&q0.y);
    float2 f2 = __half22float2(*(__half2*)&q0.z);
    float2 f3 = __half22float2(*(__half2*)&q0.w);
    float2 f4 = __half22float2(*(__half2*)&q1.x);
    float2 f5 = __half22float2(*(__half2*)&q1.y);

    __half2 p0 = __floats2half2_rn(c * f0.x, c * f0.y);
    __half2 p1 = __floats2half2_rn(c * f1.x, c * f1.y);
    __half2 p2 = __floats2half2_rn(c * f2.x, c * f2.y);
    __half2 p3 = __floats2half2_rn(c * f3.x, c * f3.y);
    __half2 p4 = __floats2half2_rn(c * f4.x, c * f4.y);
    __half2 p5 = __floats2half2_rn(c * f5.x, c * f5.y);

    asm volatile("red.global.add.noftz.v4.f16x2 [%0], {%1,%2,%3,%4};"
                 :: "l"(ap),
                    "r"(*(unsigned*)&p0), "r"(*(unsigned*)&p1),
                    "r"(*(unsigned*)&p2), "r"(*(unsigned*)&p3) : "memory");
    asm volatile("red.global.add.noftz.v2.f16x2 [%0], {%1,%2};"
                 :: "l"(ap + 8),
                    "r"(*(unsigned*)&p4), "r"(*(unsigned*)&p5) : "memory");
}

// ---------------------------------------------------------------------------
// Persistent cooperative kernel: all four phases with grid.sync() between.
// Phase bodies are verbatim from the previous 4-kernel version.
// ---------------------------------------------------------------------------
__global__ void __launch_bounds__(256) k_fused(
    const float* __restrict__ x,
    const int* __restrict__ src, const int* __restrict__ dst,
    const float* __restrict__ ew,
    const float* __restrict__ att,
    const float* __restrict__ czw, const float* __restrict__ czb,
    const float* __restrict__ Lz,  const float* __restrict__ lzb,
    const float* __restrict__ chw, const float* __restrict__ chb,
    const float* __restrict__ Lh,  const float* __restrict__ lhb,
    const float* __restrict__ head_w, const float* __restrict__ head_b,
    float* __restrict__ out, int N, int E)
{
    cg::grid_group gg = cg::this_grid();
    const int T    = gridDim.x * blockDim.x;
    const int gtid = blockIdx.x * blockDim.x + threadIdx.x;

    // ---- params fold: block 0, first warp (done before first grid sync) ----
    if (blockIdx.x == 0 && threadIdx.x < HIDDEN) {
        int c = threadIdx.x;
        float vz = 0.f, cz = 0.f, vh = 0.f, ch = 0.f;
        #pragma unroll
        for (int j = 0; j < HIDDEN; j++) {
            vz += czw[j] * Lz[j * HIDDEN + c];
            cz += czb[j] * Lz[j * HIDDEN + c];
            vh += chw[j] * Lh[j * HIDDEN + c];
            ch += chb[j] * Lh[j * HIDDEN + c];
        }
        g_p[c]       = vz * 0.5f;            // pre-halved for sigmoid->tanh identity
        g_p[32 + c]  = (cz + lzb[c]) * 0.5f;
        g_p[64 + c]  = vh;
        g_p[96 + c]  = ch + lhb[c];
        g_p[128 + c] = head_w[c];
        if (c == 0) {
            float m = att[0];
            for (int t = 1; t < PERIODS; t++) m = fmaxf(m, att[t]);
            float ex[PERIODS];
            float s = 0.f;
            for (int t = 0; t < PERIODS; t++) { ex[t] = __expf(att[t] - m); s += ex[t]; }
            float inv = 1.0f / s;
            for (int t = 0; t < PERIODS; t++) g_p[160 + t] = ex[t] * inv;
            g_p[172] = head_b[0];
        }
    }

    // ---- phase 1: deg[dst] += ew  (4 edges/thread, grid-stride) ----
    const int nquad = E >> 2;
    for (int q = gtid; q < nquad; q += T) {
        int i = q * 4;
        int4   d4 = *(const int4*)(dst + i);
        float4 w4 = *(const float4*)(ew + i);
        atomicAdd(&g_deg[d4.x], w4.x);
        atomicAdd(&g_deg[d4.y], w4.y);
        atomicAdd(&g_deg[d4.z], w4.z);
        atomicAdd(&g_deg[d4.w], w4.w);
    }
    for (int i = (E & ~3) + gtid; i < E; i += T)
        atomicAdd(&g_deg[dst[i]], ew[i]);
    gg.sync();

    // ---- phase 2: dinv = (1+deg)^{-1/2}; xs_h = fp16(dinv*x); reset deg ----
    const int n2 = N >> 1;
    const float4* x4 = (const float4*)x;
    for (int p = gtid; p < n2; p += T) {
        float2 dg = *(const float2*)(g_deg + p * 2);
        float2 di; di.x = rsqrtf(1.0f + dg.x); di.y = rsqrtf(1.0f + dg.y);
        *(float2*)(g_deg + p * 2)  = make_float2(0.f, 0.f);   // restore zero-invariant
        *(float2*)(g_dinv + p * 2) = di;
        __half2* xshv = (__half2*)(g_xsh + p * 2 * ROWPAD);
        #pragma unroll
        for (int k = 0; k < 6; k++) {                 // 6 float4 = 2 rows of x
            float dd = (k < 3) ? di.x : di.y;
            int half_off = (k < 3) ? (k * 4) : (ROWPAD + (k - 3) * 4);
            float4 v = x4[p * 6 + k];
            xshv[half_off / 2 + 0] = __floats2half2_rn(dd * v.x, dd * v.y);
            xshv[half_off / 2 + 1] = __floats2half2_rn(dd * v.z, dd * v.w);
        }
    }
    for (int i = (N & ~1) + gtid; i < N; i += T) {    // odd-N tail
        float di = rsqrtf(1.0f + g_deg[i]);
        g_deg[i] = 0.0f;
        g_dinv[i] = di;
        __half2* xshv = (__half2*)(g_xsh + i * ROWPAD);
        #pragma unroll
        for (int k = 0; k < 3; k++) {
            float4 v = x4[i * 3 + k];
            xshv[k * 2 + 0] = __floats2half2_rn(di * v.x, di * v.y);
            xshv[k * 2 + 1] = __floats2half2_rn(di * v.z, di * v.w);
        }
    }
    gg.sync();

    // ---- phase 3: agg[dst,:] += ew * xs[src,:]  (4 edges/thread) ----
    for (int q = gtid; q < nquad; q += T) {
        int i = q * 4;
        int4   s4 = *(const int4*)(src + i);
        int4   d4 = *(const int4*)(dst + i);
        float4 w4 = *(const float4*)(ew + i);
        const uint4* xa = (const uint4*)(g_xsh + s4.x * ROWPAD);
        const uint4* xb = (const uint4*)(g_xsh + s4.y * ROWPAD);
        const uint4* xc = (const uint4*)(g_xsh + s4.z * ROWPAD);
        const uint4* xd = (const uint4*)(g_xsh + s4.w * ROWPAD);
        uint4 a0 = xa[0]; uint2 a1 = ((const uint2*)xa)[2];
        uint4 b0 = xb[0]; uint2 b1 = ((const uint2*)xb)[2];
        uint4 c0 = xc[0]; uint2 c1 = ((const uint2*)xc)[2];
        uint4 e0 = xd[0]; uint2 e1 = ((const uint2*)xd)[2];
        edge_one(d4.x, w4.x, a0, a1);
        edge_one(d4.y, w4.y, b0, b1);
        edge_one(d4.z, w4.z, c0, c1);
        edge_one(d4.w, w4.w, e0, e1);
    }
    for (int i = (E & ~3) + gtid; i < E; i += T) {
        const uint4* xp = (const uint4*)(g_xsh + src[i] * ROWPAD);
        uint4 q0 = xp[0]; uint2 q1 = ((const uint2*)xp)[2];
        edge_one(dst[i], ew[i], q0, q1);
    }
    gg.sync();

    // ---- phase 4: node gate + attention + head (4 nodes/warp, grid-stride) ----
    __shared__ float sp[NPARAMS];
    __shared__ float4 sa[8][PERIODS];               // 8 warps/block; 16B aligned
    if (threadIdx.x < NPARAMS) sp[threadIdx.x] = g_p[threadIdx.x];
    __syncthreads();

    const int lane = threadIdx.x & 31;
    const int wl   = threadIdx.x >> 5;
    const int W    = T >> 5;
    const int quads = (N + 3) >> 2;
    const int r = lane >> 3, j = lane & 7;

    float vz = sp[lane],      cz = sp[32 + lane];   // pre-halved
    float vh = sp[64 + lane], ch = sp[96 + lane];
    float hwc = sp[128 + lane];
    float hb  = sp[172];

    for (int qd = (gtid >> 5); qd < quads; qd += W) {
        int base = qd * 4;
        int node = base + r;
        if (j < 6 && node < N) {
            float di = g_dinv[node];
            unsigned pair = ((const unsigned*)(g_aggh + node * ROWPAD))[j];  // t=2j,2j+1
            float2 xv = *(const float2*)(x + node * PERIODS + 2 * j);
            float2 ef = __half22float2(*(__half2*)&pair);
            float a0 = di * (ef.x + di * xv.x);
            float a1 = di * (ef.y + di * xv.y);
            float* s0 = (float*)&sa[wl][2 * j];
            s0[r]     = a0;
            s0[4 + r] = a1;
        }
        // zero restore: halves 0..11 of the 4 rows (padding never written)
        if (lane < 24) {
            int node2 = base + lane / 6;
            if (node2 < N)
                ((unsigned*)(g_aggh + node2 * ROWPAD))[lane % 6] = 0u;
        }
        __syncwarp();

        float h0 = 0.f, h1 = 0.f, h2 = 0.f, h3 = 0.f;
        #pragma unroll
        for (int t = 0; t < PERIODS; t++) {
            float p  = sp[160 + t];
            float4 q = sa[wl][t];                   // broadcast LDS.128
            float tz0 = tanhx(q.x * vz + cz), th0 = tanhx(q.x * vh + ch);
            float tz1 = tanhx(q.y * vz + cz), th1 = tanhx(q.y * vh + ch);
            float tz2 = tanhx(q.z * vz + cz), th2 = tanhx(q.z * vh + ch);
            float tz3 = tanhx(q.w * vz + cz), th3 = tanhx(q.w * vh + ch);
            h0 += p * ((0.5f - 0.5f * tz0) * th0);
            h1 += p * ((0.5f - 0.5f * tz1) * th1);
            h2 += p * ((0.5f - 0.5f * tz2) * th2);
            h3 += p * ((0.5f - 0.5f * tz3) * th3);
        }
        float v0 = fmaxf(h0, 0.f) * hwc;
        float v1 = fmaxf(h1, 0.f) * hwc;
        float v2 = fmaxf(h2, 0.f) * hwc;
        float v3 = fmaxf(h3, 0.f) * hwc;
        #pragma unroll
        for (int off = 16; off; off >>= 1) {
            v0 += __shfl_xor_sync(0xffffffffu, v0, off);
            v1 += __shfl_xor_sync(0xffffffffu, v1, off);
            v2 += __shfl_xor_sync(0xffffffffu, v2, off);
            v3 += __shfl_xor_sync(0xffffffffu, v3, off);
        }
        if (lane == 0) {
            if (base + 3 < N) {
                *(float4*)(out + base) = make_float4(v0 + hb, v1 + hb, v2 + hb, v3 + hb);
            } else {
                out[base] = v0 + hb;
                if (base + 1 < N) out[base + 1] = v1 + hb;
                if (base + 2 < N) out[base + 2] = v2 + hb;
            }
        }
        __syncwarp();    // sa[wl] reuse guard for next iteration
    }
}

extern "C" void kernel_launch(void* const* d_in, const int* in_sizes, int n_in,
                              void* d_out, int out_size) {
    const float* x    = (const float*)d_in[0];
    const int*   eidx = (const int*)d_in[1];   // int32 (JAX x64 disabled)
    const float* ew   = (const float*)d_in[2];
    const float* att  = (const float*)d_in[3];
    const float* czw  = (const float*)d_in[4];
    const float* czb  = (const float*)d_in[5];
    const float* lzw  = (const float*)d_in[6];
    const float* lzb  = (const float*)d_in[7];
    // d_in[8..11]: r-gate params — provably unused (H = 0 => H*R = 0)
    const float* chw  = (const float*)d_in[12];
    const float* chb  = (const float*)d_in[13];
    const float* lhw  = (const float*)d_in[14];
    const float* lhb  = (const float*)d_in[15];
    const float* hw   = (const float*)d_in[16];
    const float* hb   = (const float*)d_in[17];
    float* out = (float*)d_out;

    int N = in_sizes[0] / PERIODS;
    int E = in_sizes[2];
    const int* src = eidx;
    const int* dst = eidx + E;

    int nsm = 0, nb = 0;
    cudaDeviceGetAttribute(&nsm, cudaDevAttrMultiProcessorCount, 0);
    cudaOccupancyMaxActiveBlocksPerMultiprocessor(&nb, k_fused, 256, 0);
    if (nb < 1) nb = 1;
    dim3 grid(nsm * nb), block(256);

    void* args[] = {
        (void*)&x, (void*)&src, (void*)&dst, (void*)&ew, (void*)&att,
        (void*)&czw, (void*)&czb, (void*)&lzw, (void*)&lzb,
        (void*)&chw, (void*)&chb, (void*)&lhw, (void*)&lhb,
        (void*)&hw, (void*)&hb, (void*)&out, (void*)&N, (void*)&E
    };
    cudaLaunchCooperativeKernel((const void*)k_fused, grid, block, args, 0, 0);
}

// round 17
// speedup vs baseline: 1.3164x; 1.3164x over previous
#include <cuda_runtime.h>
#include <cuda_fp16.h>
#include <cstdint>

#define PERIODS 12
#define ROWPAD 16          // xs/agg rows: 16 halves = 32B (1 sector)
#define HIDDEN 32
#define MAXN 100000
#define MAXE 1600000

// Scratch (static __device__ — zero-initialized at module load; every launch
// restores the zero-invariant itself, so no init pass is needed).
__device__ float g_deg[MAXN];                             // invariant: 0 between launches
__device__ float g_dinv[MAXN];
__device__ __align__(32) __half g_aggh[MAXN * ROWPAD];    // invariant: 0 between launches
__device__ __align__(32) __half g_xsh[MAXN * ROWPAD];     // xs = dinv*x in fp16

// Params as a flat float array for easy smem staging:
// [0:32) vz*0.5 | [32:64) cz*0.5 | [64:96) vh | [96:128) ch | [128:160) hw
// [160:172) probs | [172] head_b   => 173 floats
#define NPARAMS 173
__device__ float g_p[NPARAMS];

__device__ __forceinline__ float tanhx(float x) {
    float y;
    asm("tanh.approx.f32 %0, %1;" : "=f"(y) : "f"(x));
    return y;
}

// ---------------------------------------------------------------------------
// Fused: blocks [0, eb) accumulate deg[dst] += ew, TWO edges per thread
// (vectorized stream loads). Block eb folds the gate MLPs + softmax(att).
// ---------------------------------------------------------------------------
__global__ void k_deg_params(int e, int eb,
                         const int* __restrict__ dst, const float* __restrict__ ew,
                         const float* __restrict__ att,
                         const float* __restrict__ czw, const float* __restrict__ czb,
                         const float* __restrict__ Lz,  const float* __restrict__ lzb,
                         const float* __restrict__ chw, const float* __restrict__ chb,
                         const float* __restrict__ Lh,  const float* __restrict__ lhb,
                         const float* __restrict__ head_w, const float* __restrict__ head_b) {
    if (blockIdx.x < (unsigned)eb) {
        int i = (blockIdx.x * blockDim.x + threadIdx.x) * 2;
        if (i + 1 < e) {
            int2   d2 = *(const int2*)(dst + i);
            float2 w2 = *(const float2*)(ew + i);
            atomicAdd(&g_deg[d2.x], w2.x);
            atomicAdd(&g_deg[d2.y], w2.y);
        } else if (i < e) {
            atomicAdd(&g_deg[dst[i]], ew[i]);
        }
        return;
    }
    // params block
    int c = threadIdx.x;
    if (c < HIDDEN) {
        float vz = 0.f, cz = 0.f, vh = 0.f, ch = 0.f;
        #pragma unroll
        for (int j = 0; j < HIDDEN; j++) {
            vz += czw[j] * Lz[j * HIDDEN + c];
            cz += czb[j] * Lz[j * HIDDEN + c];
            vh += chw[j] * Lh[j * HIDDEN + c];
            ch += chb[j] * Lh[j * HIDDEN + c];
        }
        g_p[c]       = vz * 0.5f;            // pre-halved for the sigmoid->tanh identity
        g_p[32 + c]  = (cz + lzb[c]) * 0.5f;
        g_p[64 + c]  = vh;
        g_p[96 + c]  = ch + lhb[c];
        g_p[128 + c] = head_w[c];
    }
    if (c == 0) {
        float m = att[0];
        for (int t = 1; t < PERIODS; t++) m = fmaxf(m, att[t]);
        float ex[PERIODS];
        float s = 0.f;
        for (int t = 0; t < PERIODS; t++) { ex[t] = __expf(att[t] - m); s += ex[t]; }
        float inv = 1.0f / s;
        for (int t = 0; t < PERIODS; t++) g_p[160 + t] = ex[t] * inv;
        g_p[172] = head_b[0];
    }
}

// dinv = (1 + deg)^{-1/2} (self loop folded);  xs_h = fp16(dinv*x);
// resets g_deg to 0 for the next launch.
__global__ void k_dinv_xs(const float4* __restrict__ x, int n) {
    int i = blockIdx.x * blockDim.x + threadIdx.x;
    if (i < n) {
        float di = rsqrtf(1.0f + g_deg[i]);
        g_deg[i] = 0.0f;                          // restore zero-invariant
        g_dinv[i] = di;
        __half2* xshv = (__half2*)(g_xsh + i * ROWPAD);
        #pragma unroll
        for (int k = 0; k < 3; k++) {
            float4 v = x[i * 3 + k];              // x rows tight (12 floats)
            xshv[k * 2 + 0] = __floats2half2_rn(di * v.x, di * v.y);
            xshv[k * 2 + 1] = __floats2half2_rn(di * v.z, di * v.w);
        }
    }
}

// Per edge: agg[dst,:] += ew * xs_h[src,:]
// TWO edges per thread: vectorized int2/float2 stream loads, both gathers
// issued back-to-back (MLP=2), then v4.f16x2 + v2.f16x2 reds per edge.
__device__ __forceinline__ void edge_one(int s, int d, float c) {
    const uint4* xp = (const uint4*)(g_xsh + s * ROWPAD);
    uint4 q0 = xp[0];                       // halves 0..7
    uint2 q1 = ((const uint2*)xp)[2];       // halves 8..11
    __half* ap = g_aggh + d * ROWPAD;

    float2 f0 = __half22float2(*(__half2*)&q0.x);
    float2 f1 = __half22float2(*(__half2*)&q0.y);
    float2 f2 = __half22float2(*(__half2*)&q0.z);
    float2 f3 = __half22float2(*(__half2*)&q0.w);
    float2 f4 = __half22float2(*(__half2*)&q1.x);
    float2 f5 = __half22float2(*(__half2*)&q1.y);

    __half2 p0 = __floats2half2_rn(c * f0.x, c * f0.y);
    __half2 p1 = __floats2half2_rn(c * f1.x, c * f1.y);
    __half2 p2 = __floats2half2_rn(c * f2.x, c * f2.y);
    __half2 p3 = __floats2half2_rn(c * f3.x, c * f3.y);
    __half2 p4 = __floats2half2_rn(c * f4.x, c * f4.y);
    __half2 p5 = __floats2half2_rn(c * f5.x, c * f5.y);

    asm volatile("red.global.add.noftz.v4.f16x2 [%0], {%1,%2,%3,%4};"
                 :: "l"(ap),
                    "r"(*(unsigned*)&p0), "r"(*(unsigned*)&p1),
                    "r"(*(unsigned*)&p2), "r"(*(unsigned*)&p3) : "memory");
    asm volatile("red.global.add.noftz.v2.f16x2 [%0], {%1,%2};"
                 :: "l"(ap + 8),
                    "r"(*(unsigned*)&p4), "r"(*(unsigned*)&p5) : "memory");
}

__global__ void k_edge(const int* __restrict__ src,
                       const int* __restrict__ dst,
                       const float* __restrict__ ew,
                       int e) {
    int i = (blockIdx.x * blockDim.x + threadIdx.x) * 2;
    if (i + 1 < e) {
        int2   s2 = *(const int2*)(src + i);
        int2   d2 = *(const int2*)(dst + i);
        float2 w2 = *(const float2*)(ew + i);
        edge_one(s2.x, d2.x, w2.x);
        edge_one(s2.y, d2.y, w2.y);
    } else if (i < e) {
        edge_one(src[i], dst[i], ew[i]);
    }
}

// FOUR consecutive nodes per warp (tanh core — at MUFU floor).
// Staging: lane = (r, j) with r = lane>>3 (node), j = lane&7 (period pair, j<6):
// one coalesced LDG.32 over the 4 contiguous agg rows + one LDG.64 from x,
// a-values written transposed into float4 sa[warp][t] (LDS.128 broadcast in loop).
// a[n,t] = dinv*(agg_fp16[n,t] + dinv*x[n,t]); term = p*(0.5-0.5*tanh(xz/2))*tanh(xh).
// Resets agg rows to 0 for the next launch.
__global__ void k_node(const float* __restrict__ x, float* __restrict__ out, int n) {
    __shared__ float sp[NPARAMS];
    __shared__ float4 sa[8][PERIODS];               // 8 warps/block; 16B aligned
    if (threadIdx.x < NPARAMS) sp[threadIdx.x] = g_p[threadIdx.x];
    __syncthreads();

    int warp = (blockIdx.x * blockDim.x + threadIdx.x) >> 5;
    int wl = threadIdx.x >> 5;
    int lane = threadIdx.x & 31;
    int base = warp * 4;
    if (base >= n) return;

    int r = lane >> 3, j = lane & 7;
    int node = base + r;
    if (j < 6 && node < n) {
        float di = g_dinv[node];
        unsigned pair = ((const unsigned*)(g_aggh + node * ROWPAD))[j];  // t=2j,2j+1
        float2 xv = *(const float2*)(x + node * PERIODS + 2 * j);
        float2 ef = __half22float2(*(__half2*)&pair);
        float a0 = di * (ef.x + di * xv.x);
        float a1 = di * (ef.y + di * xv.y);
        float* s0 = (float*)&sa[wl][2 * j];
        s0[r]     = a0;                              // sa[wl][2j].{r}
        s0[4 + r] = a1;                              // sa[wl][2j+1].{r}
    }
    // zero restore: halves 0..11 of the 4 rows (24 uints), padding never written
    if (lane < 24) {
        int node2 = base + lane / 6;
        if (node2 < n)
            ((unsigned*)(g_aggh + node2 * ROWPAD))[lane % 6] = 0u;
    }
    __syncwarp();

    float vz = sp[lane],      cz = sp[32 + lane];   // pre-halved
    float vh = sp[64 + lane], ch = sp[96 + lane];

    float h0 = 0.f, h1 = 0.f, h2 = 0.f, h3 = 0.f;
    #pragma unroll
    for (int t = 0; t < PERIODS; t++) {
        float p  = sp[160 + t];
        float4 q = sa[wl][t];                       // broadcast LDS.128
        float tz0 = tanhx(q.x * vz + cz), th0 = tanhx(q.x * vh + ch);
        float tz1 = tanhx(q.y * vz + cz), th1 = tanhx(q.y * vh + ch);
        float tz2 = tanhx(q.z * vz + cz), th2 = tanhx(q.z * vh + ch);
        float tz3 = tanhx(q.w * vz + cz), th3 = tanhx(q.w * vh + ch);
        h0 += p * ((0.5f - 0.5f * tz0) * th0);
        h1 += p * ((0.5f - 0.5f * tz1) * th1);
        h2 += p * ((0.5f - 0.5f * tz2) * th2);
        h3 += p * ((0.5f - 0.5f * tz3) * th3);
    }
    float hw = sp[128 + lane];
    float v0 = fmaxf(h0, 0.f) * hw;
    float v1 = fmaxf(h1, 0.f) * hw;
    float v2 = fmaxf(h2, 0.f) * hw;
    float v3 = fmaxf(h3, 0.f) * hw;
    #pragma unroll
    for (int off = 16; off; off >>= 1) {
        v0 += __shfl_xor_sync(0xffffffffu, v0, off);
        v1 += __shfl_xor_sync(0xffffffffu, v1, off);
        v2 += __shfl_xor_sync(0xffffffffu, v2, off);
        v3 += __shfl_xor_sync(0xffffffffu, v3, off);
    }
    if (lane == 0) {
        float hb = sp[172];
        if (base + 3 < n) {
            *(float4*)(out + base) = make_float4(v0 + hb, v1 + hb, v2 + hb, v3 + hb);
        } else {
            out[base] = v0 + hb;
            if (base + 1 < n) out[base + 1] = v1 + hb;
            if (base + 2 < n) out[base + 2] = v2 + hb;
        }
    }
}

extern "C" void kernel_launch(void* const* d_in, const int* in_sizes, int n_in,
                              void* d_out, int out_size) {
    const float* x    = (const float*)d_in[0];
    const int*   eidx = (const int*)d_in[1];   // int32 (JAX x64 disabled)
    const float* ew   = (const float*)d_in[2];
    const float* att  = (const float*)d_in[3];
    const float* czw  = (const float*)d_in[4];
    const float* czb  = (const float*)d_in[5];
    const float* lzw  = (const float*)d_in[6];
    const float* lzb  = (const float*)d_in[7];
    // d_in[8..11]: r-gate params — provably unused (H = 0 => H*R = 0)
    const float* chw  = (const float*)d_in[12];
    const float* chb  = (const float*)d_in[13];
    const float* lhw  = (const float*)d_in[14];
    const float* lhb  = (const float*)d_in[15];
    const float* hw   = (const float*)d_in[16];
    const float* hb   = (const float*)d_in[17];
    float* out = (float*)d_out;

    int N = in_sizes[0] / PERIODS;
    int E = in_sizes[2];
    const int* src = eidx;
    const int* dst = eidx + E;

    int EB = (E / 2 + 255) / 256;                  // 2 edges per thread
    k_deg_params<<<EB + 1, 256>>>(E, EB, dst, ew, att, czw, czb, lzw, lzb,
                                  chw, chb, lhw, lhb, hw, hb);

    k_dinv_xs<<<(N + 255) / 256, 256>>>((const float4*)x, N);

    int ethreads = (E + 1) / 2;                    // 2 edges per thread
    k_edge<<<(ethreads + 255) / 256, 256>>>(src, dst, ew, E);

    int quads = (N + 3) / 4;                       // one warp per 4 nodes
    k_node<<<(quads * 32 + 255) / 256, 256>>>(x, out, N);
}